// round 4
// baseline (speedup 1.0000x reference)
#include <cuda_runtime.h>
#include <math.h>

#define T_VOCAB 50265
#define CTX     384
#define BS      4
#define NDS     2048

#define NQ      4                 // vocab quarters per row
#define QLEN    12567             // ceil(50265/4); last quarter is 12564

// scratch (allocation-free rule: __device__ globals)
__device__ int   g_mc[BS * NDS];
__device__ float g_w [BS * NDS];
__device__ int   g_dt[CTX * NDS];   // transposed dataset: g_dt[s*NDS + n]

// ---------------------------------------------------------------------------
// Kernel T: tiled transpose dataset (n,s) -> g_dt (s,n) so the scatter kernel
// reads token columns coalesced.
// ---------------------------------------------------------------------------
__global__ void transpose_kernel(const int* __restrict__ dataset) {
    __shared__ int tile[32][33];
    const int n0 = blockIdx.x * 32;   // 2048/32 = 64
    const int s0 = blockIdx.y * 32;   // 384/32  = 12
    const int tx = threadIdx.x, ty = threadIdx.y;  // 32 x 8
    #pragma unroll
    for (int i = 0; i < 32; i += 8)
        tile[ty + i][tx] = dataset[(n0 + ty + i) * CTX + s0 + tx];
    __syncthreads();
    #pragma unroll
    for (int i = 0; i < 32; i += 8)
        g_dt[(s0 + ty + i) * NDS + n0 + tx] = tile[tx][ty + i];
}

// ---------------------------------------------------------------------------
// Kernel A: match counts. One warp per dataset row n; vectorized int4 loads.
// ---------------------------------------------------------------------------
__global__ void mc_kernel(const int* __restrict__ input,
                          const int* __restrict__ dataset) {
    __shared__ int4 s_in[BS][CTX / 4];    // 4 x 96 int4
    const int tid = threadIdx.x;
    for (int i = tid; i < BS * CTX / 4; i += blockDim.x)
        (&s_in[0][0])[i] = ((const int4*)input)[i];
    __syncthreads();

    const int warp = tid >> 5, lane = tid & 31;
    const int n = blockIdx.x * (blockDim.x >> 5) + warp;
    const int4* row = (const int4*)(dataset + n * CTX);

    int c0 = 0, c1 = 0, c2 = 0, c3 = 0;
    #pragma unroll
    for (int i = 0; i < 3; i++) {               // 3 * 32 lanes * 4 = 384
        const int idx = lane + 32 * i;
        const int4 dv = row[idx];
        int4 a;
        a = s_in[0][idx];
        c0 += (dv.x == a.x) + (dv.y == a.y) + (dv.z == a.z) + (dv.w == a.w);
        a = s_in[1][idx];
        c1 += (dv.x == a.x) + (dv.y == a.y) + (dv.z == a.z) + (dv.w == a.w);
        a = s_in[2][idx];
        c2 += (dv.x == a.x) + (dv.y == a.y) + (dv.z == a.z) + (dv.w == a.w);
        a = s_in[3][idx];
        c3 += (dv.x == a.x) + (dv.y == a.y) + (dv.z == a.z) + (dv.w == a.w);
    }
    #pragma unroll
    for (int off = 16; off > 0; off >>= 1) {
        c0 += __shfl_down_sync(0xffffffffu, c0, off);
        c1 += __shfl_down_sync(0xffffffffu, c1, off);
        c2 += __shfl_down_sync(0xffffffffu, c2, off);
        c3 += __shfl_down_sync(0xffffffffu, c3, off);
    }
    if (lane == 0) {
        g_mc[0 * NDS + n] = c0;
        g_mc[1 * NDS + n] = c1;
        g_mc[2 * NDS + n] = c2;
        g_mc[3 * NDS + n] = c3;
    }
}

// ---------------------------------------------------------------------------
// Kernel B: softmax over the dataset axis per batch element.
// softmax(logp) depends only on mc * d, d = log(1 + t*V/(1-t)).
// ---------------------------------------------------------------------------
__global__ void softmax_kernel(const float* __restrict__ t) {
    const int b   = blockIdx.x;
    const int tid = threadIdx.x;
    const float tb = t[b];
    const float d = logf(1.0f + tb * (float)T_VOCAB / (1.0f - tb));

    __shared__ int   s_max[256];
    __shared__ float s_sum[256];

    int mymax = -1;
    for (int n = tid; n < NDS; n += 256) mymax = max(mymax, g_mc[b * NDS + n]);
    s_max[tid] = mymax;
    __syncthreads();
    for (int off = 128; off > 0; off >>= 1) {
        if (tid < off) s_max[tid] = max(s_max[tid], s_max[tid + off]);
        __syncthreads();
    }
    const int mcmax = s_max[0];

    float mysum = 0.0f;
    for (int n = tid; n < NDS; n += 256) {
        float e = expf((float)(g_mc[b * NDS + n] - mcmax) * d);
        g_w[b * NDS + n] = e;
        mysum += e;
    }
    s_sum[tid] = mysum;
    __syncthreads();
    for (int off = 128; off > 0; off >>= 1) {
        if (tid < off) s_sum[tid] += s_sum[tid + off];
        __syncthreads();
    }
    const float inv = 1.0f / s_sum[0];
    __syncthreads();
    for (int n = tid; n < NDS; n += 256) g_w[b * NDS + n] *= inv;
}

// ---------------------------------------------------------------------------
// Kernel C: one CTA per (s, b, vocab-quarter). NO shared memory.
// Phase 1: stream zeros straight to the 49 KB output quarter (STG.128,
//          full-line writes, no read-allocate).
// Phase 2: ~512 in-range global atomicAdds (REDG) into the quarter. The
//          per-wave dirty footprint (~29 MB) sits far below L2 capacity, so
//          every atomic is an L2 hit; each output line reaches DRAM once.
// occ = 8 CTAs/SM (256 thr, no smem): zero-phases of some CTAs overlap the
// atomic-latency phases of others, keeping the store pipe / DRAM saturated.
// ---------------------------------------------------------------------------
__global__ __launch_bounds__(256)
void scatter_kernel(float* __restrict__ out) {
    const int s   = blockIdx.x;
    const int b   = blockIdx.y;
    const int q   = blockIdx.z;
    const int tid = threadIdx.x;

    const int v0  = q * QLEN;
    const int len = min(QLEN, T_VOCAB - v0);

    const size_t base = ((size_t)b * CTX + (size_t)s) * (size_t)T_VOCAB + v0;
    float* orow = out + base;

    // ---- phase 1: zero the quarter (vectorized, head/tail peeled) ----
    const int mis  = (int)(base & 3);
    const int head = (4 - mis) & 3;
    if (tid < head) orow[tid] = 0.0f;

    const int vend = head + ((len - head) & ~3);
    const float4 z4 = make_float4(0.f, 0.f, 0.f, 0.f);
    for (int v = head + tid * 4; v < vend; v += 256 * 4)
        *reinterpret_cast<float4*>(orow + v) = z4;
    for (int v = vend + tid; v < len; v += 256) orow[v] = 0.0f;

    __threadfence();     // order zero-stores before atomics from other threads
    __syncthreads();

    // ---- phase 2: scatter-add in-range tokens (L2-resident lines) ----
    const int*   col = g_dt + s * NDS;     // coalesced (transposed)
    const float* w   = g_w  + b * NDS;
    #pragma unroll 4
    for (int n = tid; n < NDS; n += 256) {
        const int rel = col[n] - v0;
        if ((unsigned)rel < (unsigned)len)
            atomicAdd(orow + rel, w[n]);   // no return value -> RED.E.ADD
    }
}

// ---------------------------------------------------------------------------
extern "C" void kernel_launch(void* const* d_in, const int* in_sizes, int n_in,
                              void* d_out, int out_size) {
    const int*   input   = (const int*)d_in[0];    // (4, 384)
    const int*   dataset = (const int*)d_in[1];    // (2048, 384)
    const float* t       = (const float*)d_in[2];  // (4,)
    float* out = (float*)d_out;                    // (4, 384, 50265) f32

    // T: transpose dataset for coalesced column reads in scatter
    dim3 tgrid(NDS / 32, CTX / 32);
    transpose_kernel<<<tgrid, dim3(32, 8)>>>(dataset);

    // A: 8 warps/block, 1 warp per dataset row -> 256 blocks
    mc_kernel<<<NDS / 8, 256>>>(input, dataset);

    // B: one block per batch element
    softmax_kernel<<<BS, 256>>>(t);

    // C: one CTA per (position, batch, vocab-quarter)
    dim3 grid(CTX, BS, NQ);
    scatter_kernel<<<grid, 256>>>(out);
}